// round 16
// baseline (speedup 1.0000x reference)
#include <cuda_runtime.h>
#include <cuda_bf16.h>
#include <cstdint>

#define BB 4
#define CC 19
#define HW (512 * 1024)         // 524288
#define NPIX (BB * HW)          // 2097152
#define NBC (BB * CC)           // 76

// s = sum(exp(x - xmax)) in [1, 19]; bin on s-bits (R13-validated constants).
#define RAWB  135
#define BASES 0xFE0u            // bits(1.0f) >> 18
#define US09  0x3F8E38E4u       // bits(float(1/0.9)); p>0.9 <=> bits(s) < US09
#define LBINS 136
#define HI0   132
#define QS    32.0f
#define HSZ (CC * LBINS)        // 2584

#define NBLK 888                // 148 SMs x 6 blocks: one wave, 222 blocks/image
#define BPI  222
#define BPX  2368               // px per block (222*2368 = 525696 >= HW)
#define TPX  512                // px per tile (2 px/thread)
#define NT   5                  // tiles per block (4 full + 320-px tail)
#define STAGES (NT * CC)        // 95 (tile,channel) stages
#define DEPTH 12                // cp.async pipeline depth (stages in flight)

// ---------------- device scratch (static, zero-init at load) ----------------
__device__ unsigned long long g_hist[NBC * LBINS];  // (count<<32) | qsum
__device__ unsigned int       g_done;

// ---------------- warp suffix-scan helpers (lane-ascending bins) ------------
__device__ __forceinline__ unsigned wsuf_u(unsigned x, unsigned lane) {
#pragma unroll
    for (int d = 1; d < 32; d <<= 1) {
        unsigned y = __shfl_down_sync(0xFFFFFFFFu, x, d);
        if (lane + d < 32) x += y;
    }
    return x;
}
__device__ __forceinline__ float wsuf_f(float x, unsigned lane) {
#pragma unroll
    for (int d = 1; d < 32; d <<= 1) {
        float y = __shfl_down_sync(0xFFFFFFFFu, x, d);
        if (lane + d < 32) x += y;
    }
    return x;
}
__device__ __forceinline__ unsigned wsum_u(unsigned x) {
#pragma unroll
    for (int d = 16; d > 0; d >>= 1) x += __shfl_xor_sync(0xFFFFFFFFu, x, d);
    return x;
}
__device__ __forceinline__ float wsum_f(float x) {
#pragma unroll
    for (int d = 16; d > 0; d >>= 1) x += __shfl_xor_sync(0xFFFFFFFFu, x, d);
    return x;
}

// ---------------- deposit one pixel into the shared histogram ---------------
__device__ __forceinline__ void deposit(unsigned* shist, float S, float m, int a) {
    float s   = S * __expf(-m);                 // = sum(exp(y - m)) in [1,19]
    float nll = __logf(S) - m;                  // = log(s)
    unsigned q = __float2uint_rn(nll * QS);     // <= 95
    unsigned us = __float_as_uint(s);
    int raw = (int)(us >> 18) - (int)BASES;
    raw = raw < 0 ? 0 : (raw > RAWB - 1 ? RAWB - 1 : raw);
    int lb = raw > 3 ? 134 - raw
           : (raw == 3 ? (us < US09 ? 132 : 131) : 135 - raw);
    atomicAdd(&shist[a * LBINS + lb], (1u << 19) | q);
}

__global__ void __launch_bounds__(256, 6) k_fused(const float* __restrict__ pred,
                                                  float* __restrict__ out) {
    __shared__ float2   sbuf[DEPTH][256];       // 24 KB thread-private ring
    __shared__ unsigned shist[HSZ];             // 10.3 KB
    __shared__ float    rowloss[NBC];
    __shared__ bool     last;
    unsigned tx   = threadIdx.x;
    unsigned img  = blockIdx.x / BPI;
    unsigned pos  = blockIdx.x % BPI;
    unsigned base = pos * BPX;                  // slab start within image
    unsigned nlim = HW - base; if (nlim > BPX) nlim = BPX;   // valid px in slab
    const float* ibase = pred + (size_t)img * CC * HW;

    for (int i = tx; i < HSZ; i += 256) shist[i] = 0;
    __syncthreads();

    unsigned sbase;
    asm("{ .reg .u64 t; cvta.to.shared.u64 t, %1; cvt.u32.u64 %0, t; }"
        : "=r"(sbase) : "l"(sbuf));
    unsigned my_s = sbase + tx * 8u;            // my 8B slot within a stage buf

    // ---- issue cursor: stage = (tile, channel); runs DEPTH ahead ----------
    unsigned coff = 0;                          // channel offset (ci * HW)
    unsigned tpos = tx * 2u;                    // ti*TPX + tx*2 (slab-local px)
    int ci = 0, slot_i = 0;

#define ISSUE_ONE() do {                                                       \
        unsigned ok  = (tpos + 2u <= nlim);                                    \
        unsigned off = ok ? (coff + base + tpos) : 0u;                         \
        asm volatile("cp.async.ca.shared.global [%0], [%1], 8;"                \
                     :: "r"(my_s + (unsigned)slot_i * 2048u),                  \
                        "l"(ibase + off) : "memory");                          \
        ci++; coff += HW;                                                      \
        if (ci == CC) { ci = 0; coff = 0; tpos += TPX; }                       \
        slot_i++; if (slot_i == DEPTH) slot_i = 0;                             \
    } while (0)

#pragma unroll
    for (int k = 0; k < DEPTH; k++) {
        ISSUE_ONE();
        asm volatile("cp.async.commit_group;" ::: "memory");
    }

    // ---- main pipeline: consume stage s, issue stage s+DEPTH ---------------
    float m0 = 0.f, m1 = 0.f, S0 = 0.f, S1 = 0.f;
    int   a0 = 0, a1 = 0;
    int   cc = 0, slot_c = 0;
    unsigned dpos = tx * 2u;                    // deposit px (tc*TPX + tx*2)

#pragma unroll 1
    for (int s = 0; s < STAGES; s++) {
        asm volatile("cp.async.wait_group %0;" :: "n"(DEPTH - 1) : "memory");
        float2 v = sbuf[slot_c][tx];

        if (cc == 0) {
            m0 = v.x; m1 = v.y; a0 = 0; a1 = 0;
            S0 = __expf(v.x); S1 = __expf(v.y);
        } else {
            if (v.x > m0) { m0 = v.x; a0 = cc; }
            if (v.y > m1) { m1 = v.y; a1 = cc; }
            S0 += __expf(v.x); S1 += __expf(v.y);
        }

        if (s < STAGES - DEPTH) ISSUE_ONE();
        asm volatile("cp.async.commit_group;" ::: "memory");

        slot_c++; if (slot_c == DEPTH) slot_c = 0;
        cc++;
        if (cc == CC) {                          // tile's last channel done
            if (dpos + 2u <= nlim) {
                deposit(shist, S0, m0, a0);
                deposit(shist, S1, m1, a1);
            }
            cc = 0; dpos += TPX;
        }
    }
#undef ISSUE_ONE

    __syncthreads();
    for (int i = tx; i < HSZ; i += 256) {
        unsigned v = shist[i];
        if (v)
            atomicAdd(&g_hist[img * HSZ + i],
                      ((unsigned long long)(v >> 19) << 32) |
                       (unsigned long long)(v & 0x7FFFFu));
    }

    // ---------------- last block: per-(b,c) loss + scalar output -----------
    __threadfence();
    __syncthreads();
    if (tx == 0) last = (atomicAdd(&g_done, 1u) == NBLK - 1);
    __syncthreads();
    if (!last) return;

    unsigned w = tx >> 5, lane = tx & 31;       // 8 warps, warp-per-row
    for (int r = w; r < NBC; r += 8) {
        unsigned long long* row = g_hist + r * LBINS;
        unsigned oc[5]; float oq[5];
#pragma unroll
        for (int ch = 0; ch < 5; ch++) {
            int bin = ch * 32 + (int)lane;
            unsigned long long hh = (bin < LBINS) ? row[bin] : 0ull;
            oc[ch] = (unsigned)(hh >> 32);
            oq[ch] = (float)(unsigned)(hh & 0xFFFFFFFFull);
            if (bin < LBINS) row[bin] = 0ull;   // clean for next replay
        }
        unsigned totc = wsum_u(oc[0] + oc[1] + oc[2] + oc[3] + oc[4]);
        unsigned k = (unsigned)floorf((float)totc * 0.66f);
        float hi = wsum_f((lane >= 4 && lane < 8) ? oq[4] : 0.f);

        float loss = 0.f;
        if (k == 0) {
            loss = hi;                          // prob-mask only
        } else {
            unsigned carc = 0; float carq = 0.f;
            float found = 0.f;
#pragma unroll
            for (int ch = 4; ch >= 0; ch--) {
                unsigned sc = wsuf_u(oc[ch], lane) + carc;
                float    sq = wsuf_f(oq[ch], lane) + carq;
                unsigned nxt  = __shfl_down_sync(0xFFFFFFFFu, sc, 1);
                float    nxtq = __shfl_down_sync(0xFFFFFFFFu, sq, 1);
                if (lane == 31) { nxt = carc; nxtq = carq; }
                int bin = ch * 32 + (int)lane;
                if (bin < LBINS && sc >= k && nxt < k) {
                    found = (bin >= HI0)
                          ? hi
                          : nxtq + (float)(k - nxt) * (oq[ch] / (float)oc[ch]);
                }
                carc = __shfl_sync(0xFFFFFFFFu, sc, 0);
                carq = __shfl_sync(0xFFFFFFFFu, sq, 0);
            }
            loss = wsum_f(found);               // exactly one lane contributed
        }
        if (lane == 0) rowloss[r] = loss;
    }
    __syncthreads();

    __shared__ double dred[256];
    dred[tx] = (tx < NBC) ? (double)rowloss[tx] : 0.0;
    __syncthreads();
#pragma unroll
    for (int s = 128; s > 0; s >>= 1) {
        if (tx < s) dred[tx] += dred[tx + s];
        __syncthreads();
    }
    if (tx == 0) {
        out[0] = (float)(dred[0] * (1.0 / ((double)QS * (double)NPIX)));
        g_done = 0;                             // reset for next graph replay
    }
}

// ---------------- launcher ---------------------------------------------------
extern "C" void kernel_launch(void* const* d_in, const int* in_sizes, int n_in,
                              void* d_out, int out_size) {
    const float* pred = (const float*)d_in[0];
    float* out = (float*)d_out;
    (void)in_sizes; (void)n_in; (void)out_size;

    k_fused<<<NBLK, 256>>>(pred, out);
}

// round 17
// speedup vs baseline: 1.1452x; 1.1452x over previous
#include <cuda_runtime.h>
#include <cuda_bf16.h>
#include <cstdint>

#define BB 4
#define CC 19
#define HW (512 * 1024)         // 524288
#define NPIX (BB * HW)          // 2097152
#define NBC (BB * CC)           // 76

// s = sum(exp(x - xmax)) in [1, 19]; bin on s-bits (R13-validated constants).
#define RAWB  135
#define BASES 0xFE0u            // bits(1.0f) >> 18
#define US09  0x3F8E38E4u       // bits(float(1/0.9)); p>0.9 <=> bits(s) < US09
#define LBINS 136
#define HI0   132
#define QS    32.0f
#define HSZ (CC * LBINS)        // 2584

#define TPB   128               // threads per block
#define TILE  2048              // px per block tile
#define NBLK  1024              // 256 blocks/image * 4; 7/SM => one wave (1036)
#define BPI   256
#define CBYTES (TILE * 4)       // 8192 bytes per channel chunk

// ---------------- device scratch (static, zero-init at load) ----------------
__device__ unsigned long long g_hist[NBC * LBINS];  // (count<<32) | qsum
__device__ unsigned int       g_done;

// ---------------- warp suffix-scan helpers (lane-ascending bins) ------------
__device__ __forceinline__ unsigned wsuf_u(unsigned x, unsigned lane) {
#pragma unroll
    for (int d = 1; d < 32; d <<= 1) {
        unsigned y = __shfl_down_sync(0xFFFFFFFFu, x, d);
        if (lane + d < 32) x += y;
    }
    return x;
}
__device__ __forceinline__ float wsuf_f(float x, unsigned lane) {
#pragma unroll
    for (int d = 1; d < 32; d <<= 1) {
        float y = __shfl_down_sync(0xFFFFFFFFu, x, d);
        if (lane + d < 32) x += y;
    }
    return x;
}
__device__ __forceinline__ unsigned wsum_u(unsigned x) {
#pragma unroll
    for (int d = 16; d > 0; d >>= 1) x += __shfl_xor_sync(0xFFFFFFFFu, x, d);
    return x;
}
__device__ __forceinline__ float wsum_f(float x) {
#pragma unroll
    for (int d = 16; d > 0; d >>= 1) x += __shfl_xor_sync(0xFFFFFFFFu, x, d);
    return x;
}

// ---------------- deposit one pixel into the shared histogram ---------------
__device__ __forceinline__ void deposit(unsigned* shist, float S, float m, int a) {
    float s   = S * __expf(-m);                 // = sum(exp(y - m)) in [1,19]
    float nll = __logf(S) - m;                  // = log(s)
    unsigned q = __float2uint_rn(nll * QS);     // <= 95
    unsigned us = __float_as_uint(s);
    int raw = (int)(us >> 18) - (int)BASES;
    raw = raw < 0 ? 0 : (raw > RAWB - 1 ? RAWB - 1 : raw);
    int lb = raw > 3 ? 134 - raw
           : (raw == 3 ? (us < US09 ? 132 : 131) : 135 - raw);
    atomicAdd(&shist[a * LBINS + lb], (1u << 19) | q);
}

__global__ void __launch_bounds__(TPB, 7) k_fused(const float* __restrict__ pred,
                                                  float* __restrict__ out) {
    __shared__ __align__(16) float buf[2][TILE];    // 16 KB double buffer
    __shared__ unsigned char a_sm[TILE];            // 2 KB argmax bytes
    __shared__ unsigned shist[HSZ];                 // 10.3 KB
    __shared__ float    rowloss[NBC];
    __shared__ unsigned long long mbar[2];
    __shared__ bool     last;
    unsigned tx  = threadIdx.x;
    unsigned img = blockIdx.x >> 8;
    unsigned pos = blockIdx.x & 255u;
    const float* gsrc = pred + (size_t)img * CC * HW + pos * TILE;

    for (int i = tx; i < HSZ; i += TPB) shist[i] = 0;

    unsigned mb0, mb1, sb0, sb1;
    asm("{ .reg .u64 t; cvta.to.shared.u64 t, %1; cvt.u32.u64 %0, t; }"
        : "=r"(mb0) : "l"(&mbar[0]));
    mb1 = mb0 + 8;
    asm("{ .reg .u64 t; cvta.to.shared.u64 t, %1; cvt.u32.u64 %0, t; }"
        : "=r"(sb0) : "l"(&buf[0][0]));
    sb1 = sb0 + CBYTES;

    if (tx == 0) {
        asm volatile("mbarrier.init.shared.b64 [%0], 1;" :: "r"(mb0) : "memory");
        asm volatile("mbarrier.init.shared.b64 [%0], 1;" :: "r"(mb1) : "memory");
    }
    __syncthreads();

#define ISSUE(MB, SB, C)                                                       \
    do {                                                                       \
        asm volatile("mbarrier.arrive.expect_tx.shared.b64 _, [%0], %1;"       \
                     :: "r"(MB), "r"((unsigned)CBYTES) : "memory");            \
        asm volatile(                                                          \
            "cp.async.bulk.shared::cta.global.mbarrier::complete_tx::bytes "   \
            "[%0], [%1], %2, [%3];"                                            \
            :: "r"(SB), "l"(gsrc + (size_t)(C) * HW),                          \
               "r"((unsigned)CBYTES), "r"(MB) : "memory");                     \
    } while (0)

#define WAITP(MB, PH)                                                          \
    do {                                                                       \
        unsigned done_;                                                        \
        asm volatile(                                                          \
            "{\n\t.reg .pred p;\n\t"                                           \
            "mbarrier.try_wait.parity.acquire.cta.shared::cta.b64 p, [%1], %2;\n\t" \
            "selp.b32 %0, 1, 0, p;\n\t}"                                       \
            : "=r"(done_) : "r"(MB), "r"(PH) : "memory");                      \
        while (!done_) {                                                       \
            asm volatile(                                                      \
                "{\n\t.reg .pred p;\n\t"                                       \
                "mbarrier.try_wait.parity.acquire.cta.shared::cta.b64 p, [%1], %2, 0x989680;\n\t" \
                "selp.b32 %0, 1, 0, p;\n\t}"                                   \
                : "=r"(done_) : "r"(MB), "r"(PH) : "memory");                  \
        }                                                                      \
    } while (0)

    if (tx == 0) { ISSUE(mb0, sb0, 0); ISSUE(mb1, sb1, 1); }

    // per-thread state: 16 px = 4 groups x float4 (group g: px g*512 + 4*tx + j)
    float m[4][4], S[4][4];
#pragma unroll
    for (int g = 0; g < 4; g++)
#pragma unroll
        for (int j = 0; j < 4; j++) { m[g][j] = -1e30f; S[g][j] = 0.f; }

#pragma unroll 1
    for (int c = 0; c < CC; c++) {
        unsigned cb = (unsigned)c & 1u;
        WAITP(cb ? mb1 : mb0, ((unsigned)c >> 1) & 1u);

#pragma unroll
        for (int g = 0; g < 4; g++) {
            float4 v = *reinterpret_cast<const float4*>(&buf[cb][g * 512 + 4 * tx]);
            float vv[4] = {v.x, v.y, v.z, v.w};
#pragma unroll
            for (int j = 0; j < 4; j++) {
                if (vv[j] > m[g][j]) {
                    m[g][j] = vv[j];
                    a_sm[g * 512 + 4 * tx + j] = (unsigned char)c;
                }
                S[g][j] += __expf(vv[j]);
            }
        }
        __syncthreads();                        // all consumed buf[cb]
        if (tx == 0 && c + 2 < CC) ISSUE(cb ? mb1 : mb0, cb ? sb1 : sb0, c + 2);
    }
#undef ISSUE
#undef WAITP

    // deposit 16 px per thread
#pragma unroll
    for (int g = 0; g < 4; g++) {
        unsigned a4 = *reinterpret_cast<const unsigned*>(&a_sm[g * 512 + 4 * tx]);
        deposit(shist, S[g][0], m[g][0], (int)(a4 & 255u));
        deposit(shist, S[g][1], m[g][1], (int)((a4 >> 8) & 255u));
        deposit(shist, S[g][2], m[g][2], (int)((a4 >> 16) & 255u));
        deposit(shist, S[g][3], m[g][3], (int)(a4 >> 24));
    }
    __syncthreads();

    for (int i = tx; i < HSZ; i += TPB) {
        unsigned v = shist[i];
        if (v)
            atomicAdd(&g_hist[img * HSZ + i],
                      ((unsigned long long)(v >> 19) << 32) |
                       (unsigned long long)(v & 0x7FFFFu));
    }

    // ---------------- last block: per-(b,c) loss + scalar output -----------
    __threadfence();
    __syncthreads();
    if (tx == 0) last = (atomicAdd(&g_done, 1u) == NBLK - 1);
    __syncthreads();
    if (!last) return;

    unsigned w = tx >> 5, lane = tx & 31;       // 4 warps, warp-per-row
    for (int r = w; r < NBC; r += 4) {
        unsigned long long* row = g_hist + r * LBINS;
        unsigned oc[5]; float oq[5];
#pragma unroll
        for (int ch = 0; ch < 5; ch++) {
            int bin = ch * 32 + (int)lane;
            unsigned long long hh = (bin < LBINS) ? row[bin] : 0ull;
            oc[ch] = (unsigned)(hh >> 32);
            oq[ch] = (float)(unsigned)(hh & 0xFFFFFFFFull);
            if (bin < LBINS) row[bin] = 0ull;   // clean for next replay
        }
        unsigned totc = wsum_u(oc[0] + oc[1] + oc[2] + oc[3] + oc[4]);
        unsigned k = (unsigned)floorf((float)totc * 0.66f);
        float hi = wsum_f((lane >= 4 && lane < 8) ? oq[4] : 0.f);

        float loss = 0.f;
        if (k == 0) {
            loss = hi;                          // prob-mask only
        } else {
            unsigned carc = 0; float carq = 0.f;
            float found = 0.f;
#pragma unroll
            for (int ch = 4; ch >= 0; ch--) {
                unsigned sc = wsuf_u(oc[ch], lane) + carc;
                float    sq = wsuf_f(oq[ch], lane) + carq;
                unsigned nxt  = __shfl_down_sync(0xFFFFFFFFu, sc, 1);
                float    nxtq = __shfl_down_sync(0xFFFFFFFFu, sq, 1);
                if (lane == 31) { nxt = carc; nxtq = carq; }
                int bin = ch * 32 + (int)lane;
                if (bin < LBINS && sc >= k && nxt < k) {
                    found = (bin >= HI0)
                          ? hi
                          : nxtq + (float)(k - nxt) * (oq[ch] / (float)oc[ch]);
                }
                carc = __shfl_sync(0xFFFFFFFFu, sc, 0);
                carq = __shfl_sync(0xFFFFFFFFu, sq, 0);
            }
            loss = wsum_f(found);               // exactly one lane contributed
        }
        if (lane == 0) rowloss[r] = loss;
    }
    __syncthreads();

    __shared__ double dred[TPB];
    double acc = (tx < NBC) ? (double)rowloss[tx] : 0.0;
    dred[tx] = acc;
    __syncthreads();
#pragma unroll
    for (int s = TPB / 2; s > 0; s >>= 1) {
        if (tx < s) dred[tx] += dred[tx + s];
        __syncthreads();
    }
    if (tx == 0) {
        out[0] = (float)(dred[0] * (1.0 / ((double)QS * (double)NPIX)));
        g_done = 0;                             // reset for next graph replay
    }
}

// ---------------- launcher ---------------------------------------------------
extern "C" void kernel_launch(void* const* d_in, const int* in_sizes, int n_in,
                              void* d_out, int out_size) {
    const float* pred = (const float*)d_in[0];
    float* out = (float*)d_out;
    (void)in_sizes; (void)n_in; (void)out_size;

    k_fused<<<NBLK, TPB>>>(pred, out);
}